// round 1
// baseline (speedup 1.0000x reference)
#include <cuda_runtime.h>
#include <math.h>

#define N_TOK 2048
#define D_DIM 1024
#define E_NUM 8
#define K_TOP 2
#define H_DIM 2048
#define NK (N_TOK * K_TOP)
#define Z_COEF 1e-4f

// ---------------- scratch (device globals; no allocs allowed) ----------------
__device__ float g_h[(size_t)NK * H_DIM];        // routed hidden activations [4096, 2048]
__device__ float g_hsh[(size_t)N_TOK * H_DIM];   // shared-expert hidden       [2048, 2048]
__device__ float g_pairout[(size_t)NK * D_DIM];  // routed per-pair outputs    [4096, 1024]
__device__ int   g_topk[NK];
__device__ float g_wts[NK];
__device__ int   g_cnt[E_NUM];
__device__ int   g_off[E_NUM];
__device__ int   g_cursor[E_NUM];
__device__ int   g_rowtok[NK];
__device__ float g_roww[NK];
__device__ int   g_pos[NK];
__device__ float g_psum[E_NUM];
__device__ float g_z2;

// ---------------- init: zero per-launch accumulators ----------------
__global__ void init_kernel() {
    int t = threadIdx.x;
    if (t < E_NUM) { g_cnt[t] = 0; g_cursor[t] = 0; g_psum[t] = 0.f; }
    if (t == 0) g_z2 = 0.f;
}

// ---------------- router: one block per token ----------------
__global__ void router_kernel(const float* __restrict__ x,
                              const float* __restrict__ rw,
                              const float* __restrict__ rb) {
    int n = blockIdx.x;
    int tid = threadIdx.x;
    __shared__ float xs[D_DIM];
    __shared__ float lg[E_NUM];
    const float* xrow = x + (size_t)n * D_DIM;
    for (int i = tid; i < D_DIM; i += 256) xs[i] = xrow[i];
    __syncthreads();

    int w = tid >> 5, lane = tid & 31;   // 8 warps, warp w -> expert w
    const float* wr = rw + (size_t)w * D_DIM;
    float s = 0.f;
    for (int i = lane; i < D_DIM; i += 32) s += xs[i] * wr[i];
    #pragma unroll
    for (int o = 16; o; o >>= 1) s += __shfl_xor_sync(0xffffffff, s, o);
    if (lane == 0) lg[w] = s;
    __syncthreads();

    if (tid == 0) {
        float l[E_NUM];
        #pragma unroll
        for (int e = 0; e < E_NUM; e++) l[e] = lg[e];

        // top-2 on biased logits (strict > keeps the lowest index on ties, like lax.top_k)
        int e0 = 0; float b0 = l[0] + rb[0];
        #pragma unroll
        for (int e = 1; e < E_NUM; e++) { float be = l[e] + rb[e]; if (be > b0) { b0 = be; e0 = e; } }
        int e1 = -1; float b1 = -1e30f;
        #pragma unroll
        for (int e = 0; e < E_NUM; e++) {
            if (e == e0) continue;
            float be = l[e] + rb[e];
            if (be > b1) { b1 = be; e1 = e; }
        }

        // softmax over the two (unbiased) top logits
        float l0 = l[e0], l1 = l[e1];
        float m2 = fmaxf(l0, l1);
        float w0 = expf(l0 - m2), w1 = expf(l1 - m2);
        float inv = 1.f / (w0 + w1);
        w0 *= inv; w1 *= inv;

        // logsumexp + full softmax probs
        float mx = l[0];
        #pragma unroll
        for (int e = 1; e < E_NUM; e++) mx = fmaxf(mx, l[e]);
        float pe[E_NUM]; float se = 0.f;
        #pragma unroll
        for (int e = 0; e < E_NUM; e++) { pe[e] = expf(l[e] - mx); se += pe[e]; }
        float z = mx + logf(se);
        atomicAdd(&g_z2, z * z);
        float invse = 1.f / se;
        #pragma unroll
        for (int e = 0; e < E_NUM; e++) atomicAdd(&g_psum[e], pe[e] * invse);

        atomicAdd(&g_cnt[e0], 1);
        atomicAdd(&g_cnt[e1], 1);
        g_topk[n * 2 + 0] = e0; g_topk[n * 2 + 1] = e1;
        g_wts[n * 2 + 0]  = w0; g_wts[n * 2 + 1]  = w1;
    }
}

// ---------------- offsets + scalar losses ----------------
__global__ void finalize_router_kernel(float* __restrict__ out_scalars, int have_scalars) {
    if (threadIdx.x == 0 && blockIdx.x == 0) {
        int acc = 0;
        for (int e = 0; e < E_NUM; e++) { g_off[e] = acc; acc += g_cnt[e]; }
        if (have_scalars) {
            float lb = 0.f;
            for (int e = 0; e < E_NUM; e++)
                lb += (g_psum[e] / (float)N_TOK) * ((float)g_cnt[e] / (float)N_TOK);
            lb *= (float)E_NUM;
            out_scalars[0] = 0.f;                            // aux_loss (aux_loss_free)
            out_scalars[1] = g_z2 / (float)N_TOK * Z_COEF;   // router_z_loss
            out_scalars[2] = lb;                             // load_balance
        }
    }
}

// ---------------- scatter tokens into per-expert row groups ----------------
__global__ void scatter_kernel() {
    int i = blockIdx.x * 256 + threadIdx.x;
    if (i >= NK) return;
    int e = g_topk[i];
    int p = g_off[e] + atomicAdd(&g_cursor[e], 1);
    g_rowtok[p] = i >> 1;         // token index
    g_roww[p]   = g_wts[i];
    g_pos[i]    = p;              // deterministic map for the combine pass
}

// ---------------- fused gate+up SGEMM + SwiGLU epilogue ----------------
// BM=BN=64, BK=16, 256 threads, 4x4 micro-tile. A rows gathered via g_rowtok.
__global__ void gateup_kernel(const float* __restrict__ X,
                              const float* __restrict__ Wg,
                              const float* __restrict__ Wu,
                              int routed) {
    int e = blockIdx.z;
    int rbase = routed ? g_off[e] : 0;
    int rcnt  = routed ? g_cnt[e] : N_TOK;
    int m0 = blockIdx.y * 64;
    if (m0 >= rcnt) return;
    int n0 = blockIdx.x * 64;

    const float* wg = Wg + (routed ? (size_t)e * H_DIM * D_DIM : 0);
    const float* wu = Wu + (routed ? (size_t)e * H_DIM * D_DIM : 0);

    __shared__ float As[16][64];
    __shared__ float Bgs[16][64];
    __shared__ float Bus[16][64];

    int tid = threadIdx.x;
    int lm = tid >> 2;            // 0..63
    int lk = (tid & 3) * 4;       // 0,4,8,12

    int arow = m0 + lm;
    const float* aptr = nullptr;
    if (arow < rcnt) {
        int tok = routed ? g_rowtok[rbase + arow] : arow;
        aptr = X + (size_t)tok * D_DIM;
    }
    const float* bgp = wg + (size_t)(n0 + lm) * D_DIM;
    const float* bup = wu + (size_t)(n0 + lm) * D_DIM;

    int tx = tid & 15, ty = tid >> 4;
    float cg[4][4] = {}, cu[4][4] = {};

    for (int kt = 0; kt < D_DIM; kt += 16) {
        float4 av = aptr ? *(const float4*)(aptr + kt + lk) : make_float4(0.f, 0.f, 0.f, 0.f);
        float4 bg = *(const float4*)(bgp + kt + lk);
        float4 bu = *(const float4*)(bup + kt + lk);
        As [lk + 0][lm] = av.x; As [lk + 1][lm] = av.y; As [lk + 2][lm] = av.z; As [lk + 3][lm] = av.w;
        Bgs[lk + 0][lm] = bg.x; Bgs[lk + 1][lm] = bg.y; Bgs[lk + 2][lm] = bg.z; Bgs[lk + 3][lm] = bg.w;
        Bus[lk + 0][lm] = bu.x; Bus[lk + 1][lm] = bu.y; Bus[lk + 2][lm] = bu.z; Bus[lk + 3][lm] = bu.w;
        __syncthreads();
        #pragma unroll
        for (int k = 0; k < 16; k++) {
            float4 a4 = *(const float4*)&As [k][ty * 4];
            float4 g4 = *(const float4*)&Bgs[k][tx * 4];
            float4 u4 = *(const float4*)&Bus[k][tx * 4];
            float a[4] = { a4.x, a4.y, a4.z, a4.w };
            float gb[4] = { g4.x, g4.y, g4.z, g4.w };
            float ub[4] = { u4.x, u4.y, u4.z, u4.w };
            #pragma unroll
            for (int i = 0; i < 4; i++)
                #pragma unroll
                for (int j = 0; j < 4; j++) {
                    cg[i][j] += a[i] * gb[j];
                    cu[i][j] += a[i] * ub[j];
                }
        }
        __syncthreads();
    }

    float* Hout = routed ? g_h : g_hsh;
    #pragma unroll
    for (int i = 0; i < 4; i++) {
        int r = m0 + ty * 4 + i;
        if (r >= rcnt) continue;
        float4 hv;
        float* hp = (float*)&hv;
        #pragma unroll
        for (int j = 0; j < 4; j++) {
            float g = cg[i][j], u = cu[i][j];
            hp[j] = g * u / (1.f + expf(-g));   // silu(g)*u
        }
        *(float4*)&Hout[(size_t)(rbase + r) * H_DIM + n0 + tx * 4] = hv;
    }
}

// ---------------- down-projection SGEMM ----------------
__global__ void down_kernel(const float* __restrict__ Wd,
                            float* __restrict__ Out,   // d_out (shared mode only)
                            int routed) {
    int e = blockIdx.z;
    int rbase = routed ? g_off[e] : 0;
    int rcnt  = routed ? g_cnt[e] : N_TOK;
    int m0 = blockIdx.y * 64;
    if (m0 >= rcnt) return;
    int n0 = blockIdx.x * 64;

    const float* wd = Wd + (routed ? (size_t)e * D_DIM * H_DIM : 0);
    const float* Hin = routed ? g_h : g_hsh;

    __shared__ float As[16][64];
    __shared__ float Bs[16][64];

    int tid = threadIdx.x;
    int lm = tid >> 2;
    int lk = (tid & 3) * 4;

    int arow = m0 + lm;
    const float* aptr = (arow < rcnt) ? Hin + (size_t)(rbase + arow) * H_DIM : nullptr;
    const float* bptr = wd + (size_t)(n0 + lm) * H_DIM;

    int tx = tid & 15, ty = tid >> 4;
    float c[4][4] = {};

    for (int kt = 0; kt < H_DIM; kt += 16) {
        float4 av = aptr ? *(const float4*)(aptr + kt + lk) : make_float4(0.f, 0.f, 0.f, 0.f);
        float4 bv = *(const float4*)(bptr + kt + lk);
        As[lk + 0][lm] = av.x; As[lk + 1][lm] = av.y; As[lk + 2][lm] = av.z; As[lk + 3][lm] = av.w;
        Bs[lk + 0][lm] = bv.x; Bs[lk + 1][lm] = bv.y; Bs[lk + 2][lm] = bv.z; Bs[lk + 3][lm] = bv.w;
        __syncthreads();
        #pragma unroll
        for (int k = 0; k < 16; k++) {
            float4 a4 = *(const float4*)&As[k][ty * 4];
            float4 b4 = *(const float4*)&Bs[k][tx * 4];
            float a[4] = { a4.x, a4.y, a4.z, a4.w };
            float b[4] = { b4.x, b4.y, b4.z, b4.w };
            #pragma unroll
            for (int i = 0; i < 4; i++)
                #pragma unroll
                for (int j = 0; j < 4; j++)
                    c[i][j] += a[i] * b[j];
        }
        __syncthreads();
    }

    #pragma unroll
    for (int i = 0; i < 4; i++) {
        int r = m0 + ty * 4 + i;
        if (r >= rcnt) continue;
        if (routed) {
            float s = g_roww[rbase + r];
            float4 v = make_float4(c[i][0] * s, c[i][1] * s, c[i][2] * s, c[i][3] * s);
            *(float4*)&g_pairout[(size_t)(rbase + r) * D_DIM + n0 + tx * 4] = v;
        } else {
            float4 v = make_float4(c[i][0], c[i][1], c[i][2], c[i][3]);
            *(float4*)&Out[(size_t)r * D_DIM + n0 + tx * 4] = v;
        }
    }
}

// ---------------- combine: out = shared + pair0 + pair1 (deterministic) ----------------
__global__ void combine_kernel(float* __restrict__ out) {
    int i4 = blockIdx.x * 256 + threadIdx.x;
    const int total4 = N_TOK * D_DIM / 4;
    if (i4 >= total4) return;
    int n  = i4 / (D_DIM / 4);
    int d4 = i4 % (D_DIM / 4);
    int p0 = g_pos[n * 2 + 0];
    int p1 = g_pos[n * 2 + 1];
    const float4* pr = (const float4*)g_pairout;
    float4 o = ((float4*)out)[i4];
    float4 a = pr[(size_t)p0 * (D_DIM / 4) + d4];
    float4 b = pr[(size_t)p1 * (D_DIM / 4) + d4];
    o.x += a.x + b.x; o.y += a.y + b.y; o.z += a.z + b.z; o.w += a.w + b.w;
    ((float4*)out)[i4] = o;
}

// ---------------- launch ----------------
extern "C" void kernel_launch(void* const* d_in, const int* in_sizes, int n_in,
                              void* d_out, int out_size) {
    const float* x      = (const float*)d_in[0];
    const float* rw     = (const float*)d_in[1];
    const float* rb     = (const float*)d_in[2];
    const float* gate_w = (const float*)d_in[3];
    const float* up_w   = (const float*)d_in[4];
    const float* down_w = (const float*)d_in[5];
    const float* shg    = (const float*)d_in[6];
    const float* shu    = (const float*)d_in[7];
    const float* shd    = (const float*)d_in[8];
    float* out = (float*)d_out;

    const int hid_elems = N_TOK * D_DIM;
    int have_scalars = (out_size >= hid_elems + 3) ? 1 : 0;

    init_kernel<<<1, 32>>>();
    router_kernel<<<N_TOK, 256>>>(x, rw, rb);
    finalize_router_kernel<<<1, 32>>>(out + hid_elems, have_scalars);
    scatter_kernel<<<NK / 256, 256>>>();

    // routed experts: gate+up fused, then down (weight baked)
    dim3 gu_r(H_DIM / 64, N_TOK / 64, E_NUM);
    gateup_kernel<<<gu_r, 256>>>(x, gate_w, up_w, 1);
    dim3 dn_r(D_DIM / 64, N_TOK / 64, E_NUM);
    down_kernel<<<dn_r, 256>>>(down_w, out, 1);

    // shared expert: writes d_out directly
    dim3 gu_s(H_DIM / 64, N_TOK / 64, 1);
    gateup_kernel<<<gu_s, 256>>>(x, shg, shu, 0);
    dim3 dn_s(D_DIM / 64, N_TOK / 64, 1);
    down_kernel<<<dn_s, 256>>>(shd, out, 0);

    combine_kernel<<<(N_TOK * D_DIM / 4 + 255) / 256, 256>>>(out);
}

// round 3
// speedup vs baseline: 5.7772x; 5.7772x over previous
#include <cuda_runtime.h>
#include <cuda_fp16.h>
#include <math.h>
#include <stdint.h>

#define N_TOK 2048
#define D_DIM 1024
#define E_NUM 8
#define K_TOP 2
#define H_DIM 2048
#define NK (N_TOK*K_TOP)
#define Z_COEF 1e-4f

// ---------------- fp16 scratch (device globals; no allocs allowed) ----------------
__device__ __half g_x16[(size_t)N_TOK*D_DIM];
__device__ __half g_wg16[(size_t)E_NUM*H_DIM*D_DIM];
__device__ __half g_wu16[(size_t)E_NUM*H_DIM*D_DIM];
__device__ __half g_wd16[(size_t)E_NUM*D_DIM*H_DIM];
__device__ __half g_shg16[(size_t)H_DIM*D_DIM];
__device__ __half g_shu16[(size_t)H_DIM*D_DIM];
__device__ __half g_shd16[(size_t)D_DIM*H_DIM];
__device__ __half g_h16[(size_t)NK*H_DIM];       // routed SwiGLU activations (scatter order)
__device__ __half g_hsh16[(size_t)N_TOK*H_DIM];  // shared-expert activations
__device__ float  g_pairout[(size_t)NK*D_DIM];   // routed per-pair outputs (fp32)

// ---------------- router scratch ----------------
__device__ int   g_topk[NK];
__device__ float g_wts[NK];
__device__ int   g_cnt[E_NUM];
__device__ int   g_off[E_NUM];
__device__ int   g_cursor[E_NUM];
__device__ int   g_rowtok[NK];
__device__ float g_roww[NK];
__device__ int   g_pos[NK];
__device__ float g_psum[E_NUM];
__device__ float g_z2;

// ============================ PTX helpers ============================
__device__ __forceinline__ uint32_t smem_u32(const void* p){
    uint32_t a;
    asm("{ .reg .u64 t; cvta.to.shared.u64 t, %1; cvt.u32.u64 %0, t; }" : "=r"(a) : "l"(p));
    return a;
}
__device__ __forceinline__ void cp16(uint32_t dst, const void* src, uint32_t sz){
    asm volatile("cp.async.cg.shared.global [%0], [%1], 16, %2;"
                 :: "r"(dst), "l"(src), "r"(sz) : "memory");
}
__device__ __forceinline__ void cp_commit(){ asm volatile("cp.async.commit_group;" ::: "memory"); }
__device__ __forceinline__ void ldsm4(uint32_t* r, uint32_t addr){
    asm volatile("ldmatrix.sync.aligned.m8n8.x4.shared.b16 {%0,%1,%2,%3}, [%4];"
                 : "=r"(r[0]), "=r"(r[1]), "=r"(r[2]), "=r"(r[3]) : "r"(addr));
}
__device__ __forceinline__ void mma16816(float* c, const uint32_t* a, const uint32_t* b){
    asm volatile("mma.sync.aligned.m16n8k16.row.col.f32.f16.f16.f32 "
                 "{%0,%1,%2,%3}, {%4,%5,%6,%7}, {%8,%9}, {%0,%1,%2,%3};"
                 : "+f"(c[0]), "+f"(c[1]), "+f"(c[2]), "+f"(c[3])
                 : "r"(a[0]), "r"(a[1]), "r"(a[2]), "r"(a[3]), "r"(b[0]), "r"(b[1]));
}

// ============================ prepass: fp32 -> fp16 ============================
__global__ void convert_kernel(const float4* __restrict__ src, uint2* __restrict__ dst, int n4){
    int i = blockIdx.x*256 + threadIdx.x;
    if (i >= n4) return;
    float4 v = src[i];
    __half2 a = __floats2half2_rn(v.x, v.y);
    __half2 b = __floats2half2_rn(v.z, v.w);
    uint2 o;
    o.x = *(uint32_t*)&a;
    o.y = *(uint32_t*)&b;
    dst[i] = o;
}

// ============================ init ============================
__global__ void init_kernel() {
    int t = threadIdx.x;
    if (t < E_NUM) { g_cnt[t] = 0; g_cursor[t] = 0; g_psum[t] = 0.f; }
    if (t == 0) g_z2 = 0.f;
}

// ============================ router (fp32, exact) ============================
__global__ void router_kernel(const float* __restrict__ x,
                              const float* __restrict__ rw,
                              const float* __restrict__ rb) {
    int n = blockIdx.x;
    int tid = threadIdx.x;
    __shared__ float xs[D_DIM];
    __shared__ float lg[E_NUM];
    const float* xrow = x + (size_t)n * D_DIM;
    for (int i = tid; i < D_DIM; i += 256) xs[i] = xrow[i];
    __syncthreads();

    int w = tid >> 5, lane = tid & 31;
    const float* wr = rw + (size_t)w * D_DIM;
    float s = 0.f;
    for (int i = lane; i < D_DIM; i += 32) s += xs[i] * wr[i];
    #pragma unroll
    for (int o = 16; o; o >>= 1) s += __shfl_xor_sync(0xffffffff, s, o);
    if (lane == 0) lg[w] = s;
    __syncthreads();

    if (tid == 0) {
        float l[E_NUM];
        #pragma unroll
        for (int e = 0; e < E_NUM; e++) l[e] = lg[e];

        int e0 = 0; float b0 = l[0] + rb[0];
        #pragma unroll
        for (int e = 1; e < E_NUM; e++) { float be = l[e] + rb[e]; if (be > b0) { b0 = be; e0 = e; } }
        int e1 = -1; float b1 = -1e30f;
        #pragma unroll
        for (int e = 0; e < E_NUM; e++) {
            if (e == e0) continue;
            float be = l[e] + rb[e];
            if (be > b1) { b1 = be; e1 = e; }
        }

        float l0 = l[e0], l1 = l[e1];
        float m2 = fmaxf(l0, l1);
        float w0 = expf(l0 - m2), w1 = expf(l1 - m2);
        float inv = 1.f / (w0 + w1);
        w0 *= inv; w1 *= inv;

        float mx = l[0];
        #pragma unroll
        for (int e = 1; e < E_NUM; e++) mx = fmaxf(mx, l[e]);
        float pe[E_NUM]; float se = 0.f;
        #pragma unroll
        for (int e = 0; e < E_NUM; e++) { pe[e] = expf(l[e] - mx); se += pe[e]; }
        float z = mx + logf(se);
        atomicAdd(&g_z2, z * z);
        float invse = 1.f / se;
        #pragma unroll
        for (int e = 0; e < E_NUM; e++) atomicAdd(&g_psum[e], pe[e] * invse);

        atomicAdd(&g_cnt[e0], 1);
        atomicAdd(&g_cnt[e1], 1);
        g_topk[n * 2 + 0] = e0; g_topk[n * 2 + 1] = e1;
        g_wts[n * 2 + 0]  = w0; g_wts[n * 2 + 1]  = w1;
    }
}

__global__ void finalize_router_kernel(float* __restrict__ out_scalars, int have_scalars) {
    if (threadIdx.x == 0 && blockIdx.x == 0) {
        int acc = 0;
        for (int e = 0; e < E_NUM; e++) { g_off[e] = acc; acc += g_cnt[e]; }
        if (have_scalars) {
            float lb = 0.f;
            for (int e = 0; e < E_NUM; e++)
                lb += (g_psum[e] / (float)N_TOK) * ((float)g_cnt[e] / (float)N_TOK);
            lb *= (float)E_NUM;
            out_scalars[0] = 0.f;
            out_scalars[1] = g_z2 / (float)N_TOK * Z_COEF;
            out_scalars[2] = lb;
        }
    }
}

__global__ void scatter_kernel() {
    int i = blockIdx.x * 256 + threadIdx.x;
    if (i >= NK) return;
    int e = g_topk[i];
    int p = g_off[e] + atomicAdd(&g_cursor[e], 1);
    g_rowtok[p] = i >> 1;
    g_roww[p]   = g_wts[i];
    g_pos[i]    = p;
}

// ============================ tensor-core GEMMs (mma.sync HMMA) ============================
// Tile: BM=128, BN=64, BK=32. 8 warps as 4(M) x 2(N); warp tile 32x32 per output.
// smem rows padded to 40 halves (80B) -> conflict-free ldmatrix.
#define LDR 80
#define GU_BG 10240
#define GU_BU 15360
#define GU_STG 20480
#define DN_B  10240
#define DN_STG 15360

__global__ __launch_bounds__(256) void gateup_mma() {
    int grp = blockIdx.z;
    bool routed = grp < E_NUM;
    int rbase = routed ? g_off[grp] : 0;
    int rcnt  = routed ? g_cnt[grp] : N_TOK;
    int m0 = blockIdx.y * 128;
    if (m0 >= rcnt) return;
    int n0 = blockIdx.x * 64;

    const __half* Wg = routed ? g_wg16 + (size_t)grp * H_DIM * D_DIM : g_shg16;
    const __half* Wu = routed ? g_wu16 + (size_t)grp * H_DIM * D_DIM : g_shu16;
    __half* Hout = routed ? g_h16 : g_hsh16;

    __shared__ __align__(16) char smem[2 * GU_STG];
    uint32_t sb = smem_u32(smem);
    int tid = threadIdx.x;

    // per-thread cp.async assignments
    int rA0 = tid >> 2, rA1 = rA0 + 64, seg = tid & 3;
    const __half *asrc0 = g_x16, *asrc1 = g_x16;
    uint32_t av0 = 0, av1 = 0;
    if (m0 + rA0 < rcnt) {
        int tk = routed ? g_rowtok[rbase + m0 + rA0] : m0 + rA0;
        asrc0 = g_x16 + (size_t)tk * D_DIM + seg * 8; av0 = 16;
    }
    if (m0 + rA1 < rcnt) {
        int tk = routed ? g_rowtok[rbase + m0 + rA1] : m0 + rA1;
        asrc1 = g_x16 + (size_t)tk * D_DIM + seg * 8; av1 = 16;
    }
    const __half* gsrc = Wg + (size_t)(n0 + rA0) * D_DIM + seg * 8;
    const __half* usrc = Wu + (size_t)(n0 + rA0) * D_DIM + seg * 8;
    uint32_t dA0 = sb + rA0 * LDR + seg * 16;
    uint32_t dA1 = sb + rA1 * LDR + seg * 16;
    uint32_t dG  = sb + GU_BG + rA0 * LDR + seg * 16;
    uint32_t dU  = sb + GU_BU + rA0 * LDR + seg * 16;

    auto load_stage = [&](int s) {
        uint32_t o = (uint32_t)(s & 1) * GU_STG;
        int koff = s * 32;
        cp16(dA0 + o, asrc0 + koff, av0);
        cp16(dA1 + o, asrc1 + koff, av1);
        cp16(dG + o,  gsrc + koff, 16);
        cp16(dU + o,  usrc + koff, 16);
        cp_commit();
    };

    load_stage(0);
    load_stage(1);

    int warp = tid >> 5, lane = tid & 31;
    int wm = warp & 3, wn = warp >> 2;
    int g = lane >> 3;
    int brow = ((g >> 1) << 3) + (lane & 7);
    int bks = (g & 1) << 4;

    float cg[2][4][4] = {}, cu[2][4][4] = {};
    const int S = D_DIM / 32;

    #pragma unroll 1
    for (int s = 0; s < S; s++) {
        if (s < S - 1) asm volatile("cp.async.wait_group 1;" ::: "memory");
        else           asm volatile("cp.async.wait_group 0;" ::: "memory");
        __syncthreads();
        uint32_t o = sb + (uint32_t)(s & 1) * GU_STG;

        uint32_t a[2][2][4];
        #pragma unroll
        for (int mt = 0; mt < 2; mt++)
            #pragma unroll
            for (int kt = 0; kt < 2; kt++)
                ldsm4(a[mt][kt], o + (wm * 32 + mt * 16 + (lane & 15)) * LDR + kt * 32 + (lane >> 4) * 16);

        uint32_t bg[2][2][4], bu[2][2][4];
        #pragma unroll
        for (int nt = 0; nt < 2; nt++)
            #pragma unroll
            for (int kt = 0; kt < 2; kt++) {
                uint32_t ro = (wn * 32 + nt * 16 + brow) * LDR + kt * 32 + bks;
                ldsm4(bg[nt][kt], o + GU_BG + ro);
                ldsm4(bu[nt][kt], o + GU_BU + ro);
            }

        #pragma unroll
        for (int mt = 0; mt < 2; mt++)
            #pragma unroll
            for (int nt = 0; nt < 2; nt++)
                #pragma unroll
                for (int kt = 0; kt < 2; kt++) {
                    mma16816(cg[mt][nt * 2 + 0], a[mt][kt], &bg[nt][kt][0]);
                    mma16816(cg[mt][nt * 2 + 1], a[mt][kt], &bg[nt][kt][2]);
                    mma16816(cu[mt][nt * 2 + 0], a[mt][kt], &bu[nt][kt][0]);
                    mma16816(cu[mt][nt * 2 + 1], a[mt][kt], &bu[nt][kt][2]);
                }
        __syncthreads();
        if (s + 2 < S) load_stage(s + 2);
    }

    // epilogue: SwiGLU, fp16 store
    #pragma unroll
    for (int mt = 0; mt < 2; mt++) {
        int rbaserow = m0 + wm * 32 + mt * 16 + (lane >> 2);
        #pragma unroll
        for (int h = 0; h < 2; h++) {
            int r = rbaserow + h * 8;
            if (r >= rcnt) continue;
            __half* hp = Hout + (size_t)(rbase + r) * H_DIM + n0 + wn * 32 + (lane & 3) * 2;
            #pragma unroll
            for (int j = 0; j < 4; j++) {
                float g0 = cg[mt][j][h * 2 + 0], g1 = cg[mt][j][h * 2 + 1];
                float u0 = cu[mt][j][h * 2 + 0], u1 = cu[mt][j][h * 2 + 1];
                float h0 = g0 * u0 / (1.f + __expf(-g0));
                float h1 = g1 * u1 / (1.f + __expf(-g1));
                *(__half2*)(hp + j * 8) = __floats2half2_rn(h0, h1);
            }
        }
    }
}

__global__ __launch_bounds__(256) void down_mma(float* __restrict__ Out) {
    int grp = blockIdx.z;
    bool routed = grp < E_NUM;
    int rbase = routed ? g_off[grp] : 0;
    int rcnt  = routed ? g_cnt[grp] : N_TOK;
    int m0 = blockIdx.y * 128;
    if (m0 >= rcnt) return;
    int n0 = blockIdx.x * 64;

    const __half* Wd  = routed ? g_wd16 + (size_t)grp * D_DIM * H_DIM : g_shd16;
    const __half* Hin = routed ? g_h16 : g_hsh16;

    __shared__ __align__(16) char smem[2 * DN_STG];
    uint32_t sb = smem_u32(smem);
    int tid = threadIdx.x;

    int rA0 = tid >> 2, rA1 = rA0 + 64, seg = tid & 3;
    const __half *asrc0 = Hin, *asrc1 = Hin;
    uint32_t av0 = 0, av1 = 0;
    if (m0 + rA0 < rcnt) { asrc0 = Hin + (size_t)(rbase + m0 + rA0) * H_DIM + seg * 8; av0 = 16; }
    if (m0 + rA1 < rcnt) { asrc1 = Hin + (size_t)(rbase + m0 + rA1) * H_DIM + seg * 8; av1 = 16; }
    const __half* bsrc = Wd + (size_t)(n0 + rA0) * H_DIM + seg * 8;
    uint32_t dA0 = sb + rA0 * LDR + seg * 16;
    uint32_t dA1 = sb + rA1 * LDR + seg * 16;
    uint32_t dB  = sb + DN_B + rA0 * LDR + seg * 16;

    auto load_stage = [&](int s) {
        uint32_t o = (uint32_t)(s & 1) * DN_STG;
        int koff = s * 32;
        cp16(dA0 + o, asrc0 + koff, av0);
        cp16(dA1 + o, asrc1 + koff, av1);
        cp16(dB + o,  bsrc + koff, 16);
        cp_commit();
    };

    load_stage(0);
    load_stage(1);

    int warp = tid >> 5, lane = tid & 31;
    int wm = warp & 3, wn = warp >> 2;
    int g = lane >> 3;
    int brow = ((g >> 1) << 3) + (lane & 7);
    int bks = (g & 1) << 4;

    float c[2][4][4] = {};
    const int S = H_DIM / 32;

    #pragma unroll 1
    for (int s = 0; s < S; s++) {
        if (s < S - 1) asm volatile("cp.async.wait_group 1;" ::: "memory");
        else           asm volatile("cp.async.wait_group 0;" ::: "memory");
        __syncthreads();
        uint32_t o = sb + (uint32_t)(s & 1) * DN_STG;

        uint32_t a[2][2][4];
        #pragma unroll
        for (int mt = 0; mt < 2; mt++)
            #pragma unroll
            for (int kt = 0; kt < 2; kt++)
                ldsm4(a[mt][kt], o + (wm * 32 + mt * 16 + (lane & 15)) * LDR + kt * 32 + (lane >> 4) * 16);

        uint32_t b[2][2][4];
        #pragma unroll
        for (int nt = 0; nt < 2; nt++)
            #pragma unroll
            for (int kt = 0; kt < 2; kt++)
                ldsm4(b[nt][kt], o + DN_B + (wn * 32 + nt * 16 + brow) * LDR + kt * 32 + bks);

        #pragma unroll
        for (int mt = 0; mt < 2; mt++)
            #pragma unroll
            for (int nt = 0; nt < 2; nt++)
                #pragma unroll
                for (int kt = 0; kt < 2; kt++) {
                    mma16816(c[mt][nt * 2 + 0], a[mt][kt], &b[nt][kt][0]);
                    mma16816(c[mt][nt * 2 + 1], a[mt][kt], &b[nt][kt][2]);
                }
        __syncthreads();
        if (s + 2 < S) load_stage(s + 2);
    }

    #pragma unroll
    for (int mt = 0; mt < 2; mt++) {
        int rbaserow = m0 + wm * 32 + mt * 16 + (lane >> 2);
        #pragma unroll
        for (int h = 0; h < 2; h++) {
            int r = rbaserow + h * 8;
            if (r >= rcnt) continue;
            float w = routed ? g_roww[rbase + r] : 1.f;
            float* op = (routed ? g_pairout + (size_t)(rbase + r) * D_DIM
                                : Out + (size_t)r * D_DIM)
                        + n0 + wn * 32 + (lane & 3) * 2;
            #pragma unroll
            for (int j = 0; j < 4; j++) {
                float2 v = make_float2(c[mt][j][h * 2 + 0] * w, c[mt][j][h * 2 + 1] * w);
                *(float2*)(op + j * 8) = v;
            }
        }
    }
}

// ============================ combine ============================
__global__ void combine_kernel(float* __restrict__ out) {
    int i4 = blockIdx.x * 256 + threadIdx.x;
    const int total4 = N_TOK * D_DIM / 4;
    if (i4 >= total4) return;
    int n  = i4 / (D_DIM / 4);
    int d4 = i4 % (D_DIM / 4);
    int p0 = g_pos[n * 2 + 0];
    int p1 = g_pos[n * 2 + 1];
    const float4* pr = (const float4*)g_pairout;
    float4 o = ((float4*)out)[i4];
    float4 a = pr[(size_t)p0 * (D_DIM / 4) + d4];
    float4 b = pr[(size_t)p1 * (D_DIM / 4) + d4];
    o.x += a.x + b.x; o.y += a.y + b.y; o.z += a.z + b.z; o.w += a.w + b.w;
    ((float4*)out)[i4] = o;
}

// ============================ launch ============================
extern "C" void kernel_launch(void* const* d_in, const int* in_sizes, int n_in,
                              void* d_out, int out_size) {
    const float* x      = (const float*)d_in[0];
    const float* rw     = (const float*)d_in[1];
    const float* rb     = (const float*)d_in[2];
    const float* gate_w = (const float*)d_in[3];
    const float* up_w   = (const float*)d_in[4];
    const float* down_w = (const float*)d_in[5];
    const float* shg    = (const float*)d_in[6];
    const float* shu    = (const float*)d_in[7];
    const float* shd    = (const float*)d_in[8];
    float* out = (float*)d_out;

    const int hid_elems = N_TOK * D_DIM;
    int have_scalars = (out_size >= hid_elems + 3) ? 1 : 0;

    void *p_x16, *p_wg16, *p_wu16, *p_wd16, *p_shg16, *p_shu16, *p_shd16;
    cudaGetSymbolAddress(&p_x16,  g_x16);
    cudaGetSymbolAddress(&p_wg16, g_wg16);
    cudaGetSymbolAddress(&p_wu16, g_wu16);
    cudaGetSymbolAddress(&p_wd16, g_wd16);
    cudaGetSymbolAddress(&p_shg16, g_shg16);
    cudaGetSymbolAddress(&p_shu16, g_shu16);
    cudaGetSymbolAddress(&p_shd16, g_shd16);

    init_kernel<<<1, 32>>>();

    const int n4_small = N_TOK * D_DIM / 4;
    const int n4_big   = E_NUM * H_DIM * D_DIM / 4;
    convert_kernel<<<n4_small / 256, 256>>>((const float4*)x,      (uint2*)p_x16,  n4_small);
    convert_kernel<<<n4_big   / 256, 256>>>((const float4*)gate_w, (uint2*)p_wg16, n4_big);
    convert_kernel<<<n4_big   / 256, 256>>>((const float4*)up_w,   (uint2*)p_wu16, n4_big);
    convert_kernel<<<n4_big   / 256, 256>>>((const float4*)down_w, (uint2*)p_wd16, n4_big);
    convert_kernel<<<n4_small / 256, 256>>>((const float4*)shg,    (uint2*)p_shg16, n4_small);
    convert_kernel<<<n4_small / 256, 256>>>((const float4*)shu,    (uint2*)p_shu16, n4_small);
    convert_kernel<<<n4_small / 256, 256>>>((const float4*)shd,    (uint2*)p_shd16, n4_small);

    router_kernel<<<N_TOK, 256>>>(x, rw, rb);
    finalize_router_kernel<<<1, 32>>>(out + hid_elems, have_scalars);
    scatter_kernel<<<NK / 256, 256>>>();

    // gate+up: N tiles over H_DIM (2048/64=32), M tiles 16, groups 9 (8 routed + shared)
    gateup_mma<<<dim3(H_DIM / 64, 16, 9), 256>>>();
    // down: N tiles over D_DIM (1024/64=16)
    down_mma<<<dim3(D_DIM / 64, 16, 9), 256>>>(out);

    combine_kernel<<<(N_TOK * D_DIM / 4 + 255) / 256, 256>>>(out);
}

// round 4
// speedup vs baseline: 5.8018x; 1.0043x over previous
#include <cuda_runtime.h>
#include <cuda_fp16.h>
#include <math.h>
#include <stdint.h>

#define N_TOK 2048
#define D_DIM 1024
#define E_NUM 8
#define K_TOP 2
#define H_DIM 2048
#define NK (N_TOK*K_TOP)
#define Z_COEF 1e-4f

// ---------------- fp16 scratch (device globals; no allocs allowed) ----------------
__device__ __half g_x16[(size_t)N_TOK*D_DIM];
__device__ __half g_wg16[(size_t)E_NUM*H_DIM*D_DIM];
__device__ __half g_wu16[(size_t)E_NUM*H_DIM*D_DIM];
__device__ __half g_wd16[(size_t)E_NUM*D_DIM*H_DIM];
__device__ __half g_shg16[(size_t)H_DIM*D_DIM];
__device__ __half g_shu16[(size_t)H_DIM*D_DIM];
__device__ __half g_shd16[(size_t)D_DIM*H_DIM];
__device__ __half g_h16[(size_t)NK*H_DIM];
__device__ __half g_hsh16[(size_t)N_TOK*H_DIM];
__device__ float  g_pairout[(size_t)NK*D_DIM];

// ---------------- router scratch ----------------
__device__ int   g_topk[NK];
__device__ float g_wts[NK];
__device__ int   g_cnt[E_NUM];
__device__ int   g_off[E_NUM];
__device__ int   g_cursor[E_NUM];
__device__ int   g_rowtok[NK];
__device__ float g_roww[NK];
__device__ int   g_pos[NK];
__device__ float g_psum[E_NUM];
__device__ float g_z2;

// ============================ PTX helpers ============================
__device__ __forceinline__ uint32_t smem_u32(const void* p){
    uint32_t a;
    asm("{ .reg .u64 t; cvta.to.shared.u64 t, %1; cvt.u32.u64 %0, t; }" : "=r"(a) : "l"(p));
    return a;
}
__device__ __forceinline__ void cp16(uint32_t dst, const void* src, uint32_t sz){
    asm volatile("cp.async.cg.shared.global [%0], [%1], 16, %2;"
                 :: "r"(dst), "l"(src), "r"(sz) : "memory");
}
__device__ __forceinline__ void cp_commit(){ asm volatile("cp.async.commit_group;" ::: "memory"); }
__device__ __forceinline__ void ldsm4(uint32_t* r, uint32_t addr){
    asm volatile("ldmatrix.sync.aligned.m8n8.x4.shared.b16 {%0,%1,%2,%3}, [%4];"
                 : "=r"(r[0]), "=r"(r[1]), "=r"(r[2]), "=r"(r[3]) : "r"(addr));
}
__device__ __forceinline__ void mma16816(float* c, const uint32_t* a, const uint32_t* b){
    asm volatile("mma.sync.aligned.m16n8k16.row.col.f32.f16.f16.f32 "
                 "{%0,%1,%2,%3}, {%4,%5,%6,%7}, {%8,%9}, {%0,%1,%2,%3};"
                 : "+f"(c[0]), "+f"(c[1]), "+f"(c[2]), "+f"(c[3])
                 : "r"(a[0]), "r"(a[1]), "r"(a[2]), "r"(a[3]), "r"(b[0]), "r"(b[1]));
}
#define CP_WAIT(N) asm volatile("cp.async.wait_group %0;" :: "n"(N) : "memory")

// ============================ fused prepass: fp32 -> fp16 ============================
// segment prefix boundaries in float4 units
#define C0 (N_TOK*D_DIM/4)                 // x        524288
#define CW (E_NUM*H_DIM*D_DIM/4)           // each big 4194304
#define CS (H_DIM*D_DIM/4)                 // each sh  524288
#define T1 (C0)
#define T2 (T1+CW)
#define T3 (T2+CW)
#define T4 (T3+CW)
#define T5 (T4+CS)
#define T6 (T5+CS)
#define T7 (T6+CS)

__global__ __launch_bounds__(256) void convert_all_kernel(
    const float4* __restrict__ x,  const float4* __restrict__ wg,
    const float4* __restrict__ wu, const float4* __restrict__ wd,
    const float4* __restrict__ sg, const float4* __restrict__ su,
    const float4* __restrict__ sd,
    uint2* __restrict__ dx,  uint2* __restrict__ dwg,
    uint2* __restrict__ dwu, uint2* __restrict__ dwd,
    uint2* __restrict__ dsg, uint2* __restrict__ dsu,
    uint2* __restrict__ dsd)
{
    int i = blockIdx.x * 256 + threadIdx.x;
    if (i >= T7) return;
    const float4* s; uint2* d; int o;
    if      (i < T1) { s = x;  d = dx;  o = i; }
    else if (i < T2) { s = wg; d = dwg; o = i - T1; }
    else if (i < T3) { s = wu; d = dwu; o = i - T2; }
    else if (i < T4) { s = wd; d = dwd; o = i - T3; }
    else if (i < T5) { s = sg; d = dsg; o = i - T4; }
    else if (i < T6) { s = su; d = dsu; o = i - T5; }
    else             { s = sd; d = dsd; o = i - T6; }
    float4 v = s[o];
    __half2 a = __floats2half2_rn(v.x, v.y);
    __half2 b = __floats2half2_rn(v.z, v.w);
    uint2 w;
    w.x = *(uint32_t*)&a;
    w.y = *(uint32_t*)&b;
    d[o] = w;
}

// ============================ init ============================
__global__ void init_kernel() {
    int t = threadIdx.x;
    if (t < E_NUM) { g_cnt[t] = 0; g_cursor[t] = 0; g_psum[t] = 0.f; }
    if (t == 0) g_z2 = 0.f;
}

// ============================ router (fp32, exact) ============================
__global__ void router_kernel(const float* __restrict__ x,
                              const float* __restrict__ rw,
                              const float* __restrict__ rb) {
    int n = blockIdx.x;
    int tid = threadIdx.x;
    __shared__ float xs[D_DIM];
    __shared__ float lg[E_NUM];
    const float* xrow = x + (size_t)n * D_DIM;
    for (int i = tid; i < D_DIM; i += 256) xs[i] = xrow[i];
    __syncthreads();

    int w = tid >> 5, lane = tid & 31;
    const float* wr = rw + (size_t)w * D_DIM;
    float s = 0.f;
    for (int i = lane; i < D_DIM; i += 32) s += xs[i] * wr[i];
    #pragma unroll
    for (int o = 16; o; o >>= 1) s += __shfl_xor_sync(0xffffffff, s, o);
    if (lane == 0) lg[w] = s;
    __syncthreads();

    if (tid == 0) {
        float l[E_NUM];
        #pragma unroll
        for (int e = 0; e < E_NUM; e++) l[e] = lg[e];

        int e0 = 0; float b0 = l[0] + rb[0];
        #pragma unroll
        for (int e = 1; e < E_NUM; e++) { float be = l[e] + rb[e]; if (be > b0) { b0 = be; e0 = e; } }
        int e1 = -1; float b1 = -1e30f;
        #pragma unroll
        for (int e = 0; e < E_NUM; e++) {
            if (e == e0) continue;
            float be = l[e] + rb[e];
            if (be > b1) { b1 = be; e1 = e; }
        }

        float l0 = l[e0], l1 = l[e1];
        float m2 = fmaxf(l0, l1);
        float w0 = expf(l0 - m2), w1 = expf(l1 - m2);
        float inv = 1.f / (w0 + w1);
        w0 *= inv; w1 *= inv;

        float mx = l[0];
        #pragma unroll
        for (int e = 1; e < E_NUM; e++) mx = fmaxf(mx, l[e]);
        float pe[E_NUM]; float se = 0.f;
        #pragma unroll
        for (int e = 0; e < E_NUM; e++) { pe[e] = expf(l[e] - mx); se += pe[e]; }
        float z = mx + logf(se);
        atomicAdd(&g_z2, z * z);
        float invse = 1.f / se;
        #pragma unroll
        for (int e = 0; e < E_NUM; e++) atomicAdd(&g_psum[e], pe[e] * invse);

        atomicAdd(&g_cnt[e0], 1);
        atomicAdd(&g_cnt[e1], 1);
        g_topk[n * 2 + 0] = e0; g_topk[n * 2 + 1] = e1;
        g_wts[n * 2 + 0]  = w0; g_wts[n * 2 + 1]  = w1;
    }
}

__global__ void finalize_router_kernel(float* __restrict__ out_scalars, int have_scalars) {
    if (threadIdx.x == 0 && blockIdx.x == 0) {
        int acc = 0;
        for (int e = 0; e < E_NUM; e++) { g_off[e] = acc; acc += g_cnt[e]; }
        if (have_scalars) {
            float lb = 0.f;
            for (int e = 0; e < E_NUM; e++)
                lb += (g_psum[e] / (float)N_TOK) * ((float)g_cnt[e] / (float)N_TOK);
            lb *= (float)E_NUM;
            out_scalars[0] = 0.f;
            out_scalars[1] = g_z2 / (float)N_TOK * Z_COEF;
            out_scalars[2] = lb;
        }
    }
}

__global__ void scatter_kernel() {
    int i = blockIdx.x * 256 + threadIdx.x;
    if (i >= NK) return;
    int e = g_topk[i];
    int p = g_off[e] + atomicAdd(&g_cursor[e], 1);
    g_rowtok[p] = i >> 1;
    g_roww[p]   = g_wts[i];
    g_pos[i]    = p;
}

// ============================ tensor-core GEMMs (mma.sync HMMA) ============================
// Tile: BM=128, BN=64, BK=32. 8 warps as 4(M) x 2(N); warp tile 32x32 per output.
// 3-stage cp.async pipeline. smem rows padded to 40 halves (80B).
#define LDR 80
#define GU_BG 10240
#define GU_BU 15360
#define GU_STG 20480
#define GU_SMEM (3*GU_STG)
#define DN_B  10240
#define DN_STG 15360
#define DN_SMEM (3*DN_STG)

__global__ __launch_bounds__(256, 2) void gateup_mma() {
    int grp = blockIdx.z;
    bool routed = grp < E_NUM;
    int rbase = routed ? g_off[grp] : 0;
    int rcnt  = routed ? g_cnt[grp] : N_TOK;
    int m0 = blockIdx.y * 128;
    if (m0 >= rcnt) return;
    int n0 = blockIdx.x * 64;

    const __half* Wg = routed ? g_wg16 + (size_t)grp * H_DIM * D_DIM : g_shg16;
    const __half* Wu = routed ? g_wu16 + (size_t)grp * H_DIM * D_DIM : g_shu16;
    __half* Hout = routed ? g_h16 : g_hsh16;

    extern __shared__ __align__(16) char smem[];
    uint32_t sb = smem_u32(smem);
    int tid = threadIdx.x;

    int rA0 = tid >> 2, rA1 = rA0 + 64, seg = tid & 3;
    const __half *asrc0 = g_x16, *asrc1 = g_x16;
    uint32_t av0 = 0, av1 = 0;
    if (m0 + rA0 < rcnt) {
        int tk = routed ? g_rowtok[rbase + m0 + rA0] : m0 + rA0;
        asrc0 = g_x16 + (size_t)tk * D_DIM + seg * 8; av0 = 16;
    }
    if (m0 + rA1 < rcnt) {
        int tk = routed ? g_rowtok[rbase + m0 + rA1] : m0 + rA1;
        asrc1 = g_x16 + (size_t)tk * D_DIM + seg * 8; av1 = 16;
    }
    const __half* gsrc = Wg + (size_t)(n0 + rA0) * D_DIM + seg * 8;
    const __half* usrc = Wu + (size_t)(n0 + rA0) * D_DIM + seg * 8;
    uint32_t dA0 = sb + rA0 * LDR + seg * 16;
    uint32_t dA1 = sb + rA1 * LDR + seg * 16;
    uint32_t dG  = sb + GU_BG + rA0 * LDR + seg * 16;
    uint32_t dU  = sb + GU_BU + rA0 * LDR + seg * 16;

    auto load_stage = [&](int s) {
        uint32_t o = (uint32_t)(s % 3) * GU_STG;
        int koff = s * 32;
        cp16(dA0 + o, asrc0 + koff, av0);
        cp16(dA1 + o, asrc1 + koff, av1);
        cp16(dG + o,  gsrc + koff, 16);
        cp16(dU + o,  usrc + koff, 16);
        cp_commit();
    };

    const int S = D_DIM / 32;
    load_stage(0);
    load_stage(1);
    load_stage(2);

    int warp = tid >> 5, lane = tid & 31;
    int wm = warp & 3, wn = warp >> 2;
    int g = lane >> 3;
    int brow = ((g >> 1) << 3) + (lane & 7);
    int bks = (g & 1) << 4;

    float cg[2][4][4] = {}, cu[2][4][4] = {};

    #pragma unroll 1
    for (int s = 0; s < S; s++) {
        if (s < S - 2)      CP_WAIT(2);
        else if (s == S - 2) CP_WAIT(1);
        else                 CP_WAIT(0);
        __syncthreads();
        uint32_t o = sb + (uint32_t)(s % 3) * GU_STG;

        uint32_t a[2][2][4];
        #pragma unroll
        for (int mt = 0; mt < 2; mt++)
            #pragma unroll
            for (int kt = 0; kt < 2; kt++)
                ldsm4(a[mt][kt], o + (wm * 32 + mt * 16 + (lane & 15)) * LDR + kt * 32 + (lane >> 4) * 16);

        uint32_t bg[2][2][4], bu[2][2][4];
        #pragma unroll
        for (int nt = 0; nt < 2; nt++)
            #pragma unroll
            for (int kt = 0; kt < 2; kt++) {
                uint32_t ro = (wn * 32 + nt * 16 + brow) * LDR + kt * 32 + bks;
                ldsm4(bg[nt][kt], o + GU_BG + ro);
                ldsm4(bu[nt][kt], o + GU_BU + ro);
            }

        #pragma unroll
        for (int mt = 0; mt < 2; mt++)
            #pragma unroll
            for (int nt = 0; nt < 2; nt++)
                #pragma unroll
                for (int kt = 0; kt < 2; kt++) {
                    mma16816(cg[mt][nt * 2 + 0], a[mt][kt], &bg[nt][kt][0]);
                    mma16816(cg[mt][nt * 2 + 1], a[mt][kt], &bg[nt][kt][2]);
                    mma16816(cu[mt][nt * 2 + 0], a[mt][kt], &bu[nt][kt][0]);
                    mma16816(cu[mt][nt * 2 + 1], a[mt][kt], &bu[nt][kt][2]);
                }
        __syncthreads();
        if (s + 3 < S) load_stage(s + 3);
    }

    #pragma unroll
    for (int mt = 0; mt < 2; mt++) {
        int rbaserow = m0 + wm * 32 + mt * 16 + (lane >> 2);
        #pragma unroll
        for (int h = 0; h < 2; h++) {
            int r = rbaserow + h * 8;
            if (r >= rcnt) continue;
            __half* hp = Hout + (size_t)(rbase + r) * H_DIM + n0 + wn * 32 + (lane & 3) * 2;
            #pragma unroll
            for (int j = 0; j < 4; j++) {
                float g0 = cg[mt][j][h * 2 + 0], g1 = cg[mt][j][h * 2 + 1];
                float u0 = cu[mt][j][h * 2 + 0], u1 = cu[mt][j][h * 2 + 1];
                float h0 = g0 * u0 / (1.f + __expf(-g0));
                float h1 = g1 * u1 / (1.f + __expf(-g1));
                *(__half2*)(hp + j * 8) = __floats2half2_rn(h0, h1);
            }
        }
    }
}

__global__ __launch_bounds__(256, 2) void down_mma(float* __restrict__ Out) {
    int grp = blockIdx.z;
    bool routed = grp < E_NUM;
    int rbase = routed ? g_off[grp] : 0;
    int rcnt  = routed ? g_cnt[grp] : N_TOK;
    int m0 = blockIdx.y * 128;
    if (m0 >= rcnt) return;
    int n0 = blockIdx.x * 64;

    const __half* Wd  = routed ? g_wd16 + (size_t)grp * D_DIM * H_DIM : g_shd16;
    const __half* Hin = routed ? g_h16 : g_hsh16;

    extern __shared__ __align__(16) char smem[];
    uint32_t sb = smem_u32(smem);
    int tid = threadIdx.x;

    int rA0 = tid >> 2, rA1 = rA0 + 64, seg = tid & 3;
    const __half *asrc0 = Hin, *asrc1 = Hin;
    uint32_t av0 = 0, av1 = 0;
    if (m0 + rA0 < rcnt) { asrc0 = Hin + (size_t)(rbase + m0 + rA0) * H_DIM + seg * 8; av0 = 16; }
    if (m0 + rA1 < rcnt) { asrc1 = Hin + (size_t)(rbase + m0 + rA1) * H_DIM + seg * 8; av1 = 16; }
    const __half* bsrc = Wd + (size_t)(n0 + rA0) * H_DIM + seg * 8;
    uint32_t dA0 = sb + rA0 * LDR + seg * 16;
    uint32_t dA1 = sb + rA1 * LDR + seg * 16;
    uint32_t dB  = sb + DN_B + rA0 * LDR + seg * 16;

    auto load_stage = [&](int s) {
        uint32_t o = (uint32_t)(s % 3) * DN_STG;
        int koff = s * 32;
        cp16(dA0 + o, asrc0 + koff, av0);
        cp16(dA1 + o, asrc1 + koff, av1);
        cp16(dB + o,  bsrc + koff, 16);
        cp_commit();
    };

    const int S = H_DIM / 32;
    load_stage(0);
    load_stage(1);
    load_stage(2);

    int warp = tid >> 5, lane = tid & 31;
    int wm = warp & 3, wn = warp >> 2;
    int g = lane >> 3;
    int brow = ((g >> 1) << 3) + (lane & 7);
    int bks = (g & 1) << 4;

    float c[2][4][4] = {};

    #pragma unroll 1
    for (int s = 0; s < S; s++) {
        if (s < S - 2)      CP_WAIT(2);
        else if (s == S - 2) CP_WAIT(1);
        else                 CP_WAIT(0);
        __syncthreads();
        uint32_t o = sb + (uint32_t)(s % 3) * DN_STG;

        uint32_t a[2][2][4];
        #pragma unroll
        for (int mt = 0; mt < 2; mt++)
            #pragma unroll
            for (int kt = 0; kt < 2; kt++)
                ldsm4(a[mt][kt], o + (wm * 32 + mt * 16 + (lane & 15)) * LDR + kt * 32 + (lane >> 4) * 16);

        uint32_t b[2][2][4];
        #pragma unroll
        for (int nt = 0; nt < 2; nt++)
            #pragma unroll
            for (int kt = 0; kt < 2; kt++)
                ldsm4(b[nt][kt], o + DN_B + (wn * 32 + nt * 16 + brow) * LDR + kt * 32 + bks);

        #pragma unroll
        for (int mt = 0; mt < 2; mt++)
            #pragma unroll
            for (int nt = 0; nt < 2; nt++)
                #pragma unroll
                for (int kt = 0; kt < 2; kt++) {
                    mma16816(c[mt][nt * 2 + 0], a[mt][kt], &b[nt][kt][0]);
                    mma16816(c[mt][nt * 2 + 1], a[mt][kt], &b[nt][kt][2]);
                }
        __syncthreads();
        if (s + 3 < S) load_stage(s + 3);
    }

    #pragma unroll
    for (int mt = 0; mt < 2; mt++) {
        int rbaserow = m0 + wm * 32 + mt * 16 + (lane >> 2);
        #pragma unroll
        for (int h = 0; h < 2; h++) {
            int r = rbaserow + h * 8;
            if (r >= rcnt) continue;
            float w = routed ? g_roww[rbase + r] : 1.f;
            float* op = (routed ? g_pairout + (size_t)(rbase + r) * D_DIM
                                : Out + (size_t)r * D_DIM)
                        + n0 + wn * 32 + (lane & 3) * 2;
            #pragma unroll
            for (int j = 0; j < 4; j++) {
                float2 v = make_float2(c[mt][j][h * 2 + 0] * w, c[mt][j][h * 2 + 1] * w);
                *(float2*)(op + j * 8) = v;
            }
        }
    }
}

// ============================ combine ============================
__global__ void combine_kernel(float* __restrict__ out) {
    int i4 = blockIdx.x * 256 + threadIdx.x;
    const int total4 = N_TOK * D_DIM / 4;
    if (i4 >= total4) return;
    int n  = i4 / (D_DIM / 4);
    int d4 = i4 % (D_DIM / 4);
    int p0 = g_pos[n * 2 + 0];
    int p1 = g_pos[n * 2 + 1];
    const float4* pr = (const float4*)g_pairout;
    float4 o = ((float4*)out)[i4];
    float4 a = pr[(size_t)p0 * (D_DIM / 4) + d4];
    float4 b = pr[(size_t)p1 * (D_DIM / 4) + d4];
    o.x += a.x + b.x; o.y += a.y + b.y; o.z += a.z + b.z; o.w += a.w + b.w;
    ((float4*)out)[i4] = o;
}

// ============================ launch ============================
extern "C" void kernel_launch(void* const* d_in, const int* in_sizes, int n_in,
                              void* d_out, int out_size) {
    const float* x      = (const float*)d_in[0];
    const float* rw     = (const float*)d_in[1];
    const float* rb     = (const float*)d_in[2];
    const float* gate_w = (const float*)d_in[3];
    const float* up_w   = (const float*)d_in[4];
    const float* down_w = (const float*)d_in[5];
    const float* shg    = (const float*)d_in[6];
    const float* shu    = (const float*)d_in[7];
    const float* shd    = (const float*)d_in[8];
    float* out = (float*)d_out;

    const int hid_elems = N_TOK * D_DIM;
    int have_scalars = (out_size >= hid_elems + 3) ? 1 : 0;

    void *p_x16, *p_wg16, *p_wu16, *p_wd16, *p_shg16, *p_shu16, *p_shd16;
    cudaGetSymbolAddress(&p_x16,  g_x16);
    cudaGetSymbolAddress(&p_wg16, g_wg16);
    cudaGetSymbolAddress(&p_wu16, g_wu16);
    cudaGetSymbolAddress(&p_wd16, g_wd16);
    cudaGetSymbolAddress(&p_shg16, g_shg16);
    cudaGetSymbolAddress(&p_shu16, g_shu16);
    cudaGetSymbolAddress(&p_shd16, g_shd16);

    cudaFuncSetAttribute(gateup_mma, cudaFuncAttributeMaxDynamicSharedMemorySize, GU_SMEM);
    cudaFuncSetAttribute(down_mma,   cudaFuncAttributeMaxDynamicSharedMemorySize, DN_SMEM);

    init_kernel<<<1, 32>>>();

    convert_all_kernel<<<(T7 + 255) / 256, 256>>>(
        (const float4*)x, (const float4*)gate_w, (const float4*)up_w, (const float4*)down_w,
        (const float4*)shg, (const float4*)shu, (const float4*)shd,
        (uint2*)p_x16, (uint2*)p_wg16, (uint2*)p_wu16, (uint2*)p_wd16,
        (uint2*)p_shg16, (uint2*)p_shu16, (uint2*)p_shd16);

    router_kernel<<<N_TOK, 256>>>(x, rw, rb);
    finalize_router_kernel<<<1, 32>>>(out + hid_elems, have_scalars);
    scatter_kernel<<<NK / 256, 256>>>();

    gateup_mma<<<dim3(H_DIM / 64, 16, 9), 256, GU_SMEM>>>();
    down_mma<<<dim3(D_DIM / 64, 16, 9), 256, DN_SMEM>>>(out);

    combine_kernel<<<(N_TOK * D_DIM / 4 + 255) / 256, 256>>>(out);
}

// round 5
// speedup vs baseline: 6.0876x; 1.0493x over previous
#include <cuda_runtime.h>
#include <cuda_fp16.h>
#include <math.h>
#include <stdint.h>

#define N_TOK 2048
#define D_DIM 1024
#define E_NUM 8
#define K_TOP 2
#define H_DIM 2048
#define NK (N_TOK*K_TOP)
#define Z_COEF 1e-4f

// ---------------- fp16 scratch (device globals; no allocs allowed) ----------------
__device__ __half g_x16[(size_t)N_TOK*D_DIM];
__device__ __half g_h16[(size_t)NK*H_DIM];       // routed SwiGLU activations (scatter order)
__device__ __half g_hsh16[(size_t)N_TOK*H_DIM];  // shared-expert activations
__device__ float  g_pairout[(size_t)NK*D_DIM];

// ---------------- router scratch ----------------
__device__ int   g_topk[NK];
__device__ float g_wts[NK];
__device__ int   g_cnt[E_NUM];
__device__ int   g_off[E_NUM];
__device__ int   g_cursor[E_NUM];
__device__ int   g_rowtok[NK];
__device__ float g_roww[NK];
__device__ int   g_pos[NK];
__device__ float g_psum[E_NUM];
__device__ float g_z2;

// ============================ PTX helpers ============================
__device__ __forceinline__ uint32_t smem_u32(const void* p){
    uint32_t a;
    asm("{ .reg .u64 t; cvta.to.shared.u64 t, %1; cvt.u32.u64 %0, t; }" : "=r"(a) : "l"(p));
    return a;
}
__device__ __forceinline__ void cp16(uint32_t dst, const void* src, uint32_t sz){
    asm volatile("cp.async.cg.shared.global [%0], [%1], 16, %2;"
                 :: "r"(dst), "l"(src), "r"(sz) : "memory");
}
__device__ __forceinline__ void cp_commit(){ asm volatile("cp.async.commit_group;" ::: "memory"); }
__device__ __forceinline__ void ldsm4(uint32_t* r, uint32_t addr){
    asm volatile("ldmatrix.sync.aligned.m8n8.x4.shared.b16 {%0,%1,%2,%3}, [%4];"
                 : "=r"(r[0]), "=r"(r[1]), "=r"(r[2]), "=r"(r[3]) : "r"(addr));
}
__device__ __forceinline__ void mma16816(float* c, const uint32_t* a, const uint32_t* b){
    asm volatile("mma.sync.aligned.m16n8k16.row.col.f32.f16.f16.f32 "
                 "{%0,%1,%2,%3}, {%4,%5,%6,%7}, {%8,%9}, {%0,%1,%2,%3};"
                 : "+f"(c[0]), "+f"(c[1]), "+f"(c[2]), "+f"(c[3])
                 : "r"(a[0]), "r"(a[1]), "r"(a[2]), "r"(a[3]), "r"(b[0]), "r"(b[1]));
}
#define CP_WAIT(N) asm volatile("cp.async.wait_group %0;" :: "n"(N) : "memory")

// pack 8 fp32 (2x float4) -> uint4 of 8 halves
__device__ __forceinline__ uint4 pack8(const float4 a, const float4 b){
    uint4 v;
    __half2 h0 = __floats2half2_rn(a.x, a.y);
    __half2 h1 = __floats2half2_rn(a.z, a.w);
    __half2 h2 = __floats2half2_rn(b.x, b.y);
    __half2 h3 = __floats2half2_rn(b.z, b.w);
    v.x = *(uint32_t*)&h0; v.y = *(uint32_t*)&h1;
    v.z = *(uint32_t*)&h2; v.w = *(uint32_t*)&h3;
    return v;
}

// ============================ prepass: x fp32 -> fp16 (8 MB only) ============================
__global__ void convert_x_kernel(const float4* __restrict__ src, uint2* __restrict__ dst, int n4){
    int i = blockIdx.x*256 + threadIdx.x;
    if (i >= n4) return;
    float4 v = src[i];
    __half2 a = __floats2half2_rn(v.x, v.y);
    __half2 b = __floats2half2_rn(v.z, v.w);
    uint2 o;
    o.x = *(uint32_t*)&a;
    o.y = *(uint32_t*)&b;
    dst[i] = o;
}

// ============================ init ============================
__global__ void init_kernel() {
    int t = threadIdx.x;
    if (t < E_NUM) { g_cnt[t] = 0; g_cursor[t] = 0; g_psum[t] = 0.f; }
    if (t == 0) g_z2 = 0.f;
}

// ============================ router (fp32, exact) ============================
__global__ void router_kernel(const float* __restrict__ x,
                              const float* __restrict__ rw,
                              const float* __restrict__ rb) {
    int n = blockIdx.x;
    int tid = threadIdx.x;
    __shared__ float xs[D_DIM];
    __shared__ float lg[E_NUM];
    const float* xrow = x + (size_t)n * D_DIM;
    for (int i = tid; i < D_DIM; i += 256) xs[i] = xrow[i];
    __syncthreads();

    int w = tid >> 5, lane = tid & 31;
    const float* wr = rw + (size_t)w * D_DIM;
    float s = 0.f;
    for (int i = lane; i < D_DIM; i += 32) s += xs[i] * wr[i];
    #pragma unroll
    for (int o = 16; o; o >>= 1) s += __shfl_xor_sync(0xffffffff, s, o);
    if (lane == 0) lg[w] = s;
    __syncthreads();

    if (tid == 0) {
        float l[E_NUM];
        #pragma unroll
        for (int e = 0; e < E_NUM; e++) l[e] = lg[e];

        int e0 = 0; float b0 = l[0] + rb[0];
        #pragma unroll
        for (int e = 1; e < E_NUM; e++) { float be = l[e] + rb[e]; if (be > b0) { b0 = be; e0 = e; } }
        int e1 = -1; float b1 = -1e30f;
        #pragma unroll
        for (int e = 0; e < E_NUM; e++) {
            if (e == e0) continue;
            float be = l[e] + rb[e];
            if (be > b1) { b1 = be; e1 = e; }
        }

        float l0 = l[e0], l1 = l[e1];
        float m2 = fmaxf(l0, l1);
        float w0 = expf(l0 - m2), w1 = expf(l1 - m2);
        float inv = 1.f / (w0 + w1);
        w0 *= inv; w1 *= inv;

        float mx = l[0];
        #pragma unroll
        for (int e = 1; e < E_NUM; e++) mx = fmaxf(mx, l[e]);
        float pe[E_NUM]; float se = 0.f;
        #pragma unroll
        for (int e = 0; e < E_NUM; e++) { pe[e] = expf(l[e] - mx); se += pe[e]; }
        float z = mx + logf(se);
        atomicAdd(&g_z2, z * z);
        float invse = 1.f / se;
        #pragma unroll
        for (int e = 0; e < E_NUM; e++) atomicAdd(&g_psum[e], pe[e] * invse);

        atomicAdd(&g_cnt[e0], 1);
        atomicAdd(&g_cnt[e1], 1);
        g_topk[n * 2 + 0] = e0; g_topk[n * 2 + 1] = e1;
        g_wts[n * 2 + 0]  = w0; g_wts[n * 2 + 1]  = w1;
    }
}

__global__ void finalize_router_kernel(float* __restrict__ out_scalars, int have_scalars) {
    if (threadIdx.x == 0 && blockIdx.x == 0) {
        int acc = 0;
        for (int e = 0; e < E_NUM; e++) { g_off[e] = acc; acc += g_cnt[e]; }
        if (have_scalars) {
            float lb = 0.f;
            for (int e = 0; e < E_NUM; e++)
                lb += (g_psum[e] / (float)N_TOK) * ((float)g_cnt[e] / (float)N_TOK);
            lb *= (float)E_NUM;
            out_scalars[0] = 0.f;
            out_scalars[1] = g_z2 / (float)N_TOK * Z_COEF;
            out_scalars[2] = lb;
        }
    }
}

__global__ void scatter_kernel() {
    int i = blockIdx.x * 256 + threadIdx.x;
    if (i >= NK) return;
    int e = g_topk[i];
    int p = g_off[e] + atomicAdd(&g_cursor[e], 1);
    g_rowtok[p] = i >> 1;
    g_roww[p]   = g_wts[i];
    g_pos[i]    = p;
}

// ============================ tensor-core GEMMs (mma.sync HMMA) ============================
// Tile: BM=128, BN=64, BK=32. 8 warps as 4(M) x 2(N); warp tile 32x32 per output.
// A (fp16 activations) via cp.async double-buffer; W (fp32 weights) via
// LDG->cvt->STS fp16, software-pipelined. smem rows padded to 40 halves (80B).
#define LDR 80
#define GU_BG 10240
#define GU_BU 15360
#define GU_STG 20480
#define DN_B  10240
#define DN_STG 15360

__global__ __launch_bounds__(256) void gateup_mma(
    const float* __restrict__ GateW, const float* __restrict__ UpW,
    const float* __restrict__ ShG,   const float* __restrict__ ShU)
{
    int grp = blockIdx.z;
    bool routed = grp < E_NUM;
    int rbase = routed ? g_off[grp] : 0;
    int rcnt  = routed ? g_cnt[grp] : N_TOK;
    int m0 = blockIdx.y * 128;
    if (m0 >= rcnt) return;
    int n0 = blockIdx.x * 64;

    const float* Wg = routed ? GateW + (size_t)grp * H_DIM * D_DIM : ShG;
    const float* Wu = routed ? UpW   + (size_t)grp * H_DIM * D_DIM : ShU;
    __half* Hout = routed ? g_h16 : g_hsh16;

    __shared__ __align__(16) char smem[2 * GU_STG];
    uint32_t sb = smem_u32(smem);
    int tid = threadIdx.x;

    int rA0 = tid >> 2, rA1 = rA0 + 64, seg = tid & 3;
    const __half *asrc0 = g_x16, *asrc1 = g_x16;
    uint32_t av0 = 0, av1 = 0;
    if (m0 + rA0 < rcnt) {
        int tk = routed ? g_rowtok[rbase + m0 + rA0] : m0 + rA0;
        asrc0 = g_x16 + (size_t)tk * D_DIM + seg * 8; av0 = 16;
    }
    if (m0 + rA1 < rcnt) {
        int tk = routed ? g_rowtok[rbase + m0 + rA1] : m0 + rA1;
        asrc1 = g_x16 + (size_t)tk * D_DIM + seg * 8; av1 = 16;
    }
    // weight row base (fp32): row n0+rA0, this thread covers floats [seg*8, seg*8+8)
    const float* gw = Wg + (size_t)(n0 + rA0) * D_DIM + seg * 8;
    const float* uw = Wu + (size_t)(n0 + rA0) * D_DIM + seg * 8;

    uint32_t dA0 = sb + rA0 * LDR + seg * 16;
    uint32_t dA1 = sb + rA1 * LDR + seg * 16;
    uint32_t dG  = sb + GU_BG + rA0 * LDR + seg * 16;
    uint32_t dU  = sb + GU_BU + rA0 * LDR + seg * 16;

    float4 wg0, wg1, wu0, wu1;   // staged fp32 weights for one upcoming stage
    auto ldg_w = [&](int s) {
        const float4* gp = (const float4*)(gw + s * 32);
        const float4* up = (const float4*)(uw + s * 32);
        wg0 = gp[0]; wg1 = gp[1];
        wu0 = up[0]; wu1 = up[1];
    };
    auto sts_w = [&](int buf) {
        uint32_t o = (uint32_t)buf * GU_STG;
        *(uint4*)(smem + (dG + o - sb)) = pack8(wg0, wg1);
        *(uint4*)(smem + (dU + o - sb)) = pack8(wu0, wu1);
    };
    auto cp_a = [&](int s) {
        uint32_t o = (uint32_t)(s & 1) * GU_STG;
        cp16(dA0 + o, asrc0 + s * 32, av0);
        cp16(dA1 + o, asrc1 + s * 32, av1);
        cp_commit();
    };

    const int S = D_DIM / 32;
    // prologue
    ldg_w(0); sts_w(0); cp_a(0);
    ldg_w(1); cp_a(1);

    int warp = tid >> 5, lane = tid & 31;
    int wm = warp & 3, wn = warp >> 2;
    int g = lane >> 3;
    int brow = ((g >> 1) << 3) + (lane & 7);
    int bks = (g & 1) << 4;

    float cg[2][4][4] = {}, cu[2][4][4] = {};

    #pragma unroll 1
    for (int s = 0; s < S; s++) {
        if (s + 1 < S) CP_WAIT(1);
        else           CP_WAIT(0);
        __syncthreads();
        uint32_t o = sb + (uint32_t)(s & 1) * GU_STG;

        uint32_t a[2][2][4];
        #pragma unroll
        for (int mt = 0; mt < 2; mt++)
            #pragma unroll
            for (int kt = 0; kt < 2; kt++)
                ldsm4(a[mt][kt], o + (wm * 32 + mt * 16 + (lane & 15)) * LDR + kt * 32 + (lane >> 4) * 16);

        uint32_t bg[2][2][4], bu[2][2][4];
        #pragma unroll
        for (int nt = 0; nt < 2; nt++)
            #pragma unroll
            for (int kt = 0; kt < 2; kt++) {
                uint32_t ro = (wn * 32 + nt * 16 + brow) * LDR + kt * 32 + bks;
                ldsm4(bg[nt][kt], o + GU_BG + ro);
                ldsm4(bu[nt][kt], o + GU_BU + ro);
            }

        #pragma unroll
        for (int mt = 0; mt < 2; mt++)
            #pragma unroll
            for (int nt = 0; nt < 2; nt++)
                #pragma unroll
                for (int kt = 0; kt < 2; kt++) {
                    mma16816(cg[mt][nt * 2 + 0], a[mt][kt], &bg[nt][kt][0]);
                    mma16816(cg[mt][nt * 2 + 1], a[mt][kt], &bg[nt][kt][2]);
                    mma16816(cu[mt][nt * 2 + 0], a[mt][kt], &bu[nt][kt][0]);
                    mma16816(cu[mt][nt * 2 + 1], a[mt][kt], &bu[nt][kt][2]);
                }

        if (s + 1 < S) sts_w((s + 1) & 1);   // stage s+1 weights (A already cp.async'd there)
        __syncthreads();                      // everyone done reading buf s&1
        if (s + 2 < S) { cp_a(s + 2); ldg_w(s + 2); }
    }

    #pragma unroll
    for (int mt = 0; mt < 2; mt++) {
        int rbaserow = m0 + wm * 32 + mt * 16 + (lane >> 2);
        #pragma unroll
        for (int h = 0; h < 2; h++) {
            int r = rbaserow + h * 8;
            if (r >= rcnt) continue;
            __half* hp = Hout + (size_t)(rbase + r) * H_DIM + n0 + wn * 32 + (lane & 3) * 2;
            #pragma unroll
            for (int j = 0; j < 4; j++) {
                float g0 = cg[mt][j][h * 2 + 0], g1 = cg[mt][j][h * 2 + 1];
                float u0 = cu[mt][j][h * 2 + 0], u1 = cu[mt][j][h * 2 + 1];
                float h0 = g0 * u0 / (1.f + __expf(-g0));
                float h1 = g1 * u1 / (1.f + __expf(-g1));
                *(__half2*)(hp + j * 8) = __floats2half2_rn(h0, h1);
            }
        }
    }
}

__global__ __launch_bounds__(256, 2) void down_mma(
    const float* __restrict__ DownW, const float* __restrict__ ShD,
    float* __restrict__ Out)
{
    int grp = blockIdx.z;
    bool routed = grp < E_NUM;
    int rbase = routed ? g_off[grp] : 0;
    int rcnt  = routed ? g_cnt[grp] : N_TOK;
    int m0 = blockIdx.y * 128;
    if (m0 >= rcnt) return;
    int n0 = blockIdx.x * 64;

    const float* Wd  = routed ? DownW + (size_t)grp * D_DIM * H_DIM : ShD;
    const __half* Hin = routed ? g_h16 : g_hsh16;

    __shared__ __align__(16) char smem[2 * DN_STG];
    uint32_t sb = smem_u32(smem);
    int tid = threadIdx.x;

    int rA0 = tid >> 2, rA1 = rA0 + 64, seg = tid & 3;
    const __half *asrc0 = Hin, *asrc1 = Hin;
    uint32_t av0 = 0, av1 = 0;
    if (m0 + rA0 < rcnt) { asrc0 = Hin + (size_t)(rbase + m0 + rA0) * H_DIM + seg * 8; av0 = 16; }
    if (m0 + rA1 < rcnt) { asrc1 = Hin + (size_t)(rbase + m0 + rA1) * H_DIM + seg * 8; av1 = 16; }
    const float* dw = Wd + (size_t)(n0 + rA0) * H_DIM + seg * 8;

    uint32_t dA0 = sb + rA0 * LDR + seg * 16;
    uint32_t dA1 = sb + rA1 * LDR + seg * 16;
    uint32_t dB  = sb + DN_B + rA0 * LDR + seg * 16;

    float4 wd0, wd1;
    auto ldg_w = [&](int s) {
        const float4* p = (const float4*)(dw + s * 32);
        wd0 = p[0]; wd1 = p[1];
    };
    auto sts_w = [&](int buf) {
        *(uint4*)(smem + (dB + (uint32_t)buf * DN_STG - sb)) = pack8(wd0, wd1);
    };
    auto cp_a = [&](int s) {
        uint32_t o = (uint32_t)(s & 1) * DN_STG;
        cp16(dA0 + o, asrc0 + s * 32, av0);
        cp16(dA1 + o, asrc1 + s * 32, av1);
        cp_commit();
    };

    const int S = H_DIM / 32;
    ldg_w(0); sts_w(0); cp_a(0);
    ldg_w(1); cp_a(1);

    int warp = tid >> 5, lane = tid & 31;
    int wm = warp & 3, wn = warp >> 2;
    int g = lane >> 3;
    int brow = ((g >> 1) << 3) + (lane & 7);
    int bks = (g & 1) << 4;

    float c[2][4][4] = {};

    #pragma unroll 1
    for (int s = 0; s < S; s++) {
        if (s + 1 < S) CP_WAIT(1);
        else           CP_WAIT(0);
        __syncthreads();
        uint32_t o = sb + (uint32_t)(s & 1) * DN_STG;

        uint32_t a[2][2][4];
        #pragma unroll
        for (int mt = 0; mt < 2; mt++)
            #pragma unroll
            for (int kt = 0; kt < 2; kt++)
                ldsm4(a[mt][kt], o + (wm * 32 + mt * 16 + (lane & 15)) * LDR + kt * 32 + (lane >> 4) * 16);

        uint32_t b[2][2][4];
        #pragma unroll
        for (int nt = 0; nt < 2; nt++)
            #pragma unroll
            for (int kt = 0; kt < 2; kt++)
                ldsm4(b[nt][kt], o + DN_B + (wn * 32 + nt * 16 + brow) * LDR + kt * 32 + bks);

        #pragma unroll
        for (int mt = 0; mt < 2; mt++)
            #pragma unroll
            for (int nt = 0; nt < 2; nt++)
                #pragma unroll
                for (int kt = 0; kt < 2; kt++) {
                    mma16816(c[mt][nt * 2 + 0], a[mt][kt], &b[nt][kt][0]);
                    mma16816(c[mt][nt * 2 + 1], a[mt][kt], &b[nt][kt][2]);
                }

        if (s + 1 < S) sts_w((s + 1) & 1);
        __syncthreads();
        if (s + 2 < S) { cp_a(s + 2); ldg_w(s + 2); }
    }

    #pragma unroll
    for (int mt = 0; mt < 2; mt++) {
        int rbaserow = m0 + wm * 32 + mt * 16 + (lane >> 2);
        #pragma unroll
        for (int h = 0; h < 2; h++) {
            int r = rbaserow + h * 8;
            if (r >= rcnt) continue;
            float w = routed ? g_roww[rbase + r] : 1.f;
            float* op = (routed ? g_pairout + (size_t)(rbase + r) * D_DIM
                                : Out + (size_t)r * D_DIM)
                        + n0 + wn * 32 + (lane & 3) * 2;
            #pragma unroll
            for (int j = 0; j < 4; j++) {
                float2 v = make_float2(c[mt][j][h * 2 + 0] * w, c[mt][j][h * 2 + 1] * w);
                *(float2*)(op + j * 8) = v;
            }
        }
    }
}

// ============================ combine ============================
__global__ void combine_kernel(float* __restrict__ out) {
    int i4 = blockIdx.x * 256 + threadIdx.x;
    const int total4 = N_TOK * D_DIM / 4;
    if (i4 >= total4) return;
    int n  = i4 / (D_DIM / 4);
    int d4 = i4 % (D_DIM / 4);
    int p0 = g_pos[n * 2 + 0];
    int p1 = g_pos[n * 2 + 1];
    const float4* pr = (const float4*)g_pairout;
    float4 o = ((float4*)out)[i4];
    float4 a = pr[(size_t)p0 * (D_DIM / 4) + d4];
    float4 b = pr[(size_t)p1 * (D_DIM / 4) + d4];
    o.x += a.x + b.x; o.y += a.y + b.y; o.z += a.z + b.z; o.w += a.w + b.w;
    ((float4*)out)[i4] = o;
}

// ============================ launch ============================
extern "C" void kernel_launch(void* const* d_in, const int* in_sizes, int n_in,
                              void* d_out, int out_size) {
    const float* x      = (const float*)d_in[0];
    const float* rw     = (const float*)d_in[1];
    const float* rb     = (const float*)d_in[2];
    const float* gate_w = (const float*)d_in[3];
    const float* up_w   = (const float*)d_in[4];
    const float* down_w = (const float*)d_in[5];
    const float* shg    = (const float*)d_in[6];
    const float* shu    = (const float*)d_in[7];
    const float* shd    = (const float*)d_in[8];
    float* out = (float*)d_out;

    const int hid_elems = N_TOK * D_DIM;
    int have_scalars = (out_size >= hid_elems + 3) ? 1 : 0;

    void* p_x16;
    cudaGetSymbolAddress(&p_x16, g_x16);

    init_kernel<<<1, 32>>>();

    const int n4_x = N_TOK * D_DIM / 4;
    convert_x_kernel<<<n4_x / 256, 256>>>((const float4*)x, (uint2*)p_x16, n4_x);

    router_kernel<<<N_TOK, 256>>>(x, rw, rb);
    finalize_router_kernel<<<1, 32>>>(out + hid_elems, have_scalars);
    scatter_kernel<<<NK / 256, 256>>>();

    gateup_mma<<<dim3(H_DIM / 64, 16, 9), 256>>>(gate_w, up_w, shg, shu);
    down_mma<<<dim3(D_DIM / 64, 16, 9), 256>>>(down_w, shd, out);

    combine_kernel<<<(N_TOK * D_DIM / 4 + 255) / 256, 256>>>(out);
}